// round 15
// baseline (speedup 1.0000x reference)
#include <cuda_runtime.h>
#include <cuda_bf16.h>
#include <cstdint>

// ===================== problem constants =====================
constexpr int Nn = 8192;
constexpr int Dd = 768;
constexpr int BM = 128;            // Q rows per job
constexpr int BN = 128;            // C cols per tile
constexpr int BK = 64;             // K per SMEM chunk (64 bf16 = 128B rows)
constexpr int NKC = Dd / BK;       // 12 K-chunks
constexpr int COLSPLIT = 16;       // by range
constexpr int CHUNKS = (Nn / BN) / COLSPLIT;  // 4 col tiles per job
constexpr int TOT = CHUNKS * NKC;  // 48 B-chunk iterations per job
constexpr int NJOBS = (Nn / BM) * COLSPLIT;   // 1024
// q rows pre-scaled by 20*log2(e): accumulators are base-2 logits directly
constexpr float QSCALE = 20.0f * 1.4426950408889634f;
constexpr float D2SC = 28.853900817779268f;   // 20*log2(e)
constexpr float LN2 = 0.6931471805599453f;

constexpr int A_BYTES = BM * Dd * 2;                    // 196608
constexpr int B_OFF   = A_BYTES;
constexpr int SMEM_BYTES = A_BYTES + 2 * BN * BK * 2;   // 229376

// ===================== device scratch =====================
__device__ __align__(16) __nv_bfloat16 g_qn[(size_t)Nn * Dd];
__device__ __align__(16) __nv_bfloat16 g_cn[(size_t)Nn * Dd];
__device__ float g_rows[COLSPLIT][Nn];
__device__ float g_diag[Nn];   // exact fp32 diagonal, base-2 scaled

// ===================== helpers =====================
__device__ __forceinline__ uint32_t smem_u32(const void* p) {
    uint32_t a;
    asm("{ .reg .u64 t; cvta.to.shared.u64 t, %1; cvt.u32.u64 %0, t; }"
        : "=r"(a) : "l"(p));
    return a;
}

#define SMEM_SWIZZLE_128B(o) ((o) ^ (((o) >> 3) & 0x70))

__device__ __forceinline__ void cp16(uint32_t dst, const void* src) {
    asm volatile("cp.async.cg.shared.global [%0], [%1], 16;" :: "r"(dst), "l"(src));
}
#define CP_COMMIT asm volatile("cp.async.commit_group;" ::: "memory")
#define CP_WAIT0  asm volatile("cp.async.wait_group 0;" ::: "memory")

__device__ __forceinline__ void ldm4(uint32_t* r, uint32_t addr) {
    asm volatile("ldmatrix.sync.aligned.m8n8.x4.shared.b16 {%0,%1,%2,%3}, [%4];"
        : "=r"(r[0]), "=r"(r[1]), "=r"(r[2]), "=r"(r[3]) : "r"(addr));
}

__device__ __forceinline__ void mma16816(float* d, const uint32_t* a,
                                         uint32_t b0, uint32_t b1) {
    asm volatile(
        "mma.sync.aligned.m16n8k16.row.col.f32.bf16.bf16.f32 "
        "{%0,%1,%2,%3}, {%4,%5,%6,%7}, {%8,%9}, {%0,%1,%2,%3};"
        : "+f"(d[0]), "+f"(d[1]), "+f"(d[2]), "+f"(d[3])
        : "r"(a[0]), "r"(a[1]), "r"(a[2]), "r"(a[3]), "r"(b0), "r"(b1));
}

__device__ __forceinline__ float ex2f(float x) {
    float y;
    asm("ex2.approx.f32 %0, %1;" : "=f"(y) : "f"(x));
    return y;
}

// non-CSE-able v4 global load (forces pass-2 re-load instead of keeping regs)
__device__ __forceinline__ float4 ldg4v(const float4* p) {
    float4 v;
    asm volatile("ld.global.nc.v4.f32 {%0,%1,%2,%3}, [%4];"
        : "=f"(v.x), "=f"(v.y), "=f"(v.z), "=f"(v.w) : "l"(p));
    return v;
}

// ===== kernel 1: normalize fp32 -> bf16 (q pre-scaled), exact diagonal =====
// Two-pass warp-per-row: pass 1 reduces (low reg pressure -> high occupancy),
// pass 2 re-loads (L2-hot) + scales + packed bf16x2 stores.
__global__ void __launch_bounds__(256) norm_kernel(const float* __restrict__ q,
                                                   const float* __restrict__ c) {
    const int lane = threadIdx.x & 31;
    const int row = blockIdx.x * 8 + (threadIdx.x >> 5);  // 0..8191

    const float4* qs = reinterpret_cast<const float4*>(q + (size_t)row * Dd);
    const float4* cs = reinterpret_cast<const float4*>(c + (size_t)row * Dd);

    // ---- pass 1: reduce qq / cc / qc (values not kept) ----
    float qq = 0.f, cc = 0.f, qc = 0.f;
#pragma unroll
    for (int j = 0; j < 6; j++) {
        float4 a = qs[lane + j * 32];
        float4 b = cs[lane + j * 32];
        qq += a.x * a.x + a.y * a.y + a.z * a.z + a.w * a.w;
        cc += b.x * b.x + b.y * b.y + b.z * b.z + b.w * b.w;
        qc += a.x * b.x + a.y * b.y + a.z * b.z + a.w * b.w;
    }
#pragma unroll
    for (int o = 16; o; o >>= 1) {
        qq += __shfl_xor_sync(0xFFFFFFFFu, qq, o);
        cc += __shfl_xor_sync(0xFFFFFFFFu, cc, o);
        qc += __shfl_xor_sync(0xFFFFFFFFu, qc, o);
    }
    const float nq = fmaxf(sqrtf(qq), 1e-8f);
    const float nc = fmaxf(sqrtf(cc), 1e-8f);
    if (lane == 0) g_diag[row] = D2SC * qc / (nq * nc);

    // ---- pass 2: re-load (L2-hot), scale, convert, store ----
    const float sq = QSCALE / nq, sc = 1.0f / nc;
    uint2* qd = reinterpret_cast<uint2*>(g_qn + (size_t)row * Dd);
    uint2* cd = reinterpret_cast<uint2*>(g_cn + (size_t)row * Dd);
#pragma unroll
    for (int j = 0; j < 6; j++) {
        float4 a = ldg4v(qs + lane + j * 32);
        float4 b = ldg4v(cs + lane + j * 32);
        __nv_bfloat162 q0 = __float22bfloat162_rn(make_float2(a.x * sq, a.y * sq));
        __nv_bfloat162 q1 = __float22bfloat162_rn(make_float2(a.z * sq, a.w * sq));
        __nv_bfloat162 c0 = __float22bfloat162_rn(make_float2(b.x * sc, b.y * sc));
        __nv_bfloat162 c1 = __float22bfloat162_rn(make_float2(b.z * sc, b.w * sc));
        qd[lane + j * 32] = make_uint2(*(uint32_t*)&q0, *(uint32_t*)&q1);
        cd[lane + j * 32] = make_uint2(*(uint32_t*)&c0, *(uint32_t*)&c1);
    }
}

// ===================== kernel 2: persistent fused GEMM + exp2-rowsum =====================
// grid = #SMs. Contiguous job spans (bx-major) -> A-tile reuse.
// 8 warps: 4(M) x 2(N), 32x64 warp tiles. Tile epilogues are DEFERRED:
// acc is stashed into eacc at tile end and the exp2/rowsum work is spread
// over chunks kc=0..3 of the next tile (overlaps MUFU with tensor pipe).
__global__ void __launch_bounds__(256, 1) simcse_main() {
    extern __shared__ __align__(1024) uint8_t smem[];
    uint8_t* sA = smem;           // 12 chunks of [128 rows][128B] SW128 K-major
    uint8_t* sB = smem + B_OFF;   // 2 buffers of [128 rows][128B] SW128 K-major

    const int tid = threadIdx.x;
    const int lane = tid & 31;
    const int wid = tid >> 5;
    const int warp_m = wid >> 1;   // 0..3 (32 rows each)
    const int warp_n = wid & 1;    // 0..1 (64 cols each)

    const uint32_t sA_u = smem_u32(sA);
    const uint32_t sB_u = smem_u32(sB);

    // per-lane ldmatrix base offsets (bytes, pre-swizzle) — R2/R5-validated
    const uint32_t aoff0 = (uint32_t)((lane & 15) * 128 + (lane >> 4) * 16) +
                           (uint32_t)warp_m * 4096u;
    const uint32_t boff0 = (uint32_t)(((((lane >> 4) & 1) * 8) + (lane & 7)) * 128 +
                                      ((lane >> 3) & 1) * 16) +
                           (uint32_t)warp_n * 8192u;

    const int ncta = gridDim.x;
    const int lo = (int)(((long long)blockIdx.x * NJOBS) / ncta);
    const int hi = (int)(((long long)(blockIdx.x + 1) * NJOBS) / ncta);
    int prev_bx = -1;

    float acc[2][8][4];
    float eacc[2][8][4];
#pragma unroll
    for (int mt = 0; mt < 2; mt++)
#pragma unroll
        for (int nt = 0; nt < 8; nt++)
#pragma unroll
            for (int d = 0; d < 4; d++) acc[mt][nt][d] = 0.f;

#pragma unroll 1
    for (int job = lo; job < hi; job++) {
        const int bx = job >> 4;       // row block 0..63
        const int by = job & 15;       // col split 0..15

        // ---- stage A on bx change: 128 Q rows (192KB) via cp.async ----
        if (bx != prev_bx) {
            const __nv_bfloat16* qbase = g_qn + (size_t)bx * BM * Dd;
#pragma unroll 4
            for (int i = 0; i < 48; i++) {
                int idx = tid + i * 256;        // 0..12287 (16B units)
                int kc = idx >> 10;
                int pos = idx & 1023;
                int r = pos >> 3, c = pos & 7;
                const void* src = qbase + (size_t)r * Dd + kc * BK + c * 8;
                uint32_t dst = sA_u + kc * 16384 +
                               SMEM_SWIZZLE_128B((uint32_t)(r * 128 + c * 16));
                cp16(dst, src);
            }
            prev_bx = bx;
        }

        const __nv_bfloat16* cquad = g_cn + (size_t)by * CHUNKS * BN * Dd;

        auto loadB = [&](int g, int buf) {
            const int t = g / NKC, kc = g % NKC;
            const __nv_bfloat16* cb = cquad + (size_t)t * BN * Dd + kc * BK;
#pragma unroll
            for (int i = 0; i < 4; i++) {
                int pos = tid + i * 256;        // 0..1023
                int r = pos >> 3, c = pos & 7;
                cp16(sB_u + buf * 16384 +
                         SMEM_SWIZZLE_128B((uint32_t)(r * 128 + c * 16)),
                     cb + (size_t)r * Dd + c * 8);
            }
            CP_COMMIT;
        };

        loadB(0, 0);  // (A's cp.asyncs, if any, join this commit group)

        float rsum[2][2] = {{0.f, 0.f}, {0.f, 0.f}};
        bool pending = false;

        // one 64-K chunk: wait, publish, prefetch next B, ldm+mma
        auto chunk = [&](int g, int kc) {
            const int buf = g & 1;
            CP_WAIT0;            // this chunk's B tile (and A if staged) resident
            __syncthreads();     // publish buf to all threads; protect buf^1
            if (g + 1 < TOT) loadB(g + 1, buf ^ 1);

            const uint32_t abase = sA_u + (uint32_t)kc * 16384u;
            const uint32_t bbase = sB_u + (uint32_t)buf * 16384u;

            uint32_t a[2][2][4], b[2][4][4];
#pragma unroll
            for (int mt = 0; mt < 2; mt++)
                ldm4(a[0][mt], abase + SMEM_SWIZZLE_128B(aoff0 + (uint32_t)(mt * 2048)));
#pragma unroll
            for (int ntp = 0; ntp < 4; ntp++)
                ldm4(b[0][ntp], bbase + SMEM_SWIZZLE_128B(boff0 + (uint32_t)(ntp * 2048)));

#pragma unroll
            for (int kk = 0; kk < 4; kk++) {
                const int cur = kk & 1, nxt = cur ^ 1;
                if (kk < 3) {
#pragma unroll
                    for (int mt = 0; mt < 2; mt++)
                        ldm4(a[nxt][mt], abase + SMEM_SWIZZLE_128B(
                                 aoff0 + (uint32_t)(mt * 2048 + (kk + 1) * 32)));
#pragma unroll
                    for (int ntp = 0; ntp < 4; ntp++)
                        ldm4(b[nxt][ntp], bbase + SMEM_SWIZZLE_128B(
                                 boff0 + (uint32_t)(ntp * 2048 + (kk + 1) * 32)));
                }
#pragma unroll
                for (int mt = 0; mt < 2; mt++)
#pragma unroll
                    for (int ntp = 0; ntp < 4; ntp++) {
                        mma16816(acc[mt][2 * ntp + 0], a[cur][mt],
                                 b[cur][ntp][0], b[cur][ntp][1]);
                        mma16816(acc[mt][2 * ntp + 1], a[cur][mt],
                                 b[cur][ntp][2], b[cur][ntp][3]);
                    }
            }
        };

#pragma unroll 1
        for (int t = 0; t < CHUNKS; t++) {
            // peeled kc=0..3: carry the previous tile's epilogue slices
#pragma unroll
            for (int kcp = 0; kcp < 4; kcp++) {
                chunk(t * NKC + kcp, kcp);
                if (pending) {
#pragma unroll
                    for (int mt = 0; mt < 2; mt++)
#pragma unroll
                        for (int j = 0; j < 2; j++) {
                            const int nt = 2 * kcp + j;  // static
#pragma unroll
                            for (int d = 0; d < 4; d++)
                                rsum[mt][d >> 1] += ex2f(eacc[mt][nt][d]);
                        }
                }
            }
#pragma unroll 1
            for (int kc = 4; kc < NKC; kc++) chunk(t * NKC + kc, kc);

            // tile end: stash accumulators, clear for next tile
#pragma unroll
            for (int mt = 0; mt < 2; mt++)
#pragma unroll
                for (int nt = 0; nt < 8; nt++)
#pragma unroll
                    for (int d = 0; d < 4; d++) {
                        eacc[mt][nt][d] = acc[mt][nt][d];
                        acc[mt][nt][d] = 0.f;
                    }
            pending = true;
        }

        // final (non-overlapped) epilogue for the job's last tile
#pragma unroll
        for (int mt = 0; mt < 2; mt++)
#pragma unroll
            for (int nt = 0; nt < 8; nt++)
#pragma unroll
                for (int d = 0; d < 4; d++)
                    rsum[mt][d >> 1] += ex2f(eacc[mt][nt][d]);

        // ---- per-job reduce: quad shuffle, then across the 2 N-warps ----
#pragma unroll
        for (int mt = 0; mt < 2; mt++)
#pragma unroll
            for (int h = 0; h < 2; h++) {
                float v = rsum[mt][h];
                v += __shfl_xor_sync(0xFFFFFFFFu, v, 1);
                v += __shfl_xor_sync(0xFFFFFFFFu, v, 2);
                rsum[mt][h] = v;
            }

        float* sred = (float*)sB;    // B buffers are free after last chunk
        __syncthreads();             // all warps done with compute/B reads
        if ((lane & 3) == 0) {
#pragma unroll
            for (int mt = 0; mt < 2; mt++)
#pragma unroll
                for (int h = 0; h < 2; h++) {
                    int rl = warp_m * 32 + mt * 16 + h * 8 + (lane >> 2);
                    sred[rl * 2 + warp_n] = rsum[mt][h];
                }
        }
        __syncthreads();
        if (tid < BM) g_rows[by][bx * BM + tid] = sred[tid * 2] + sred[tid * 2 + 1];
        __syncthreads();  // sred reads done before next job's loadB overwrites sB
    }
}

// ===================== kernel 3: loss reduction (1024 threads) =====================
__global__ void __launch_bounds__(1024) loss_kernel(float* __restrict__ out) {
    int tid = threadIdx.x;
    float acc = 0.f;
#pragma unroll 1
    for (int i = tid; i < Nn; i += 1024) {
        float r = 0.f;
#pragma unroll
        for (int s = 0; s < COLSPLIT; s++) r += g_rows[s][i];
        acc += logf(r) - g_diag[i] * LN2;   // diag is base-2 scaled (exact fp32)
    }
#pragma unroll
    for (int o = 16; o; o >>= 1) acc += __shfl_xor_sync(0xFFFFFFFFu, acc, o);
    __shared__ float sred[32];
    if ((tid & 31) == 0) sred[tid >> 5] = acc;
    __syncthreads();
    if (tid < 32) {
        float v = sred[tid];
#pragma unroll
        for (int o = 16; o; o >>= 1) v += __shfl_xor_sync(0xFFFFFFFFu, v, o);
        if (tid == 0) out[0] = v * (1.0f / (float)Nn);
    }
}

// ===================== launch =====================
extern "C" void kernel_launch(void* const* d_in, const int* in_sizes, int n_in,
                              void* d_out, int out_size) {
    const float* q = (const float*)d_in[0];
    const float* c = (const float*)d_in[1];
    float* out = (float*)d_out;

    cudaFuncSetAttribute(simcse_main, cudaFuncAttributeMaxDynamicSharedMemorySize,
                         SMEM_BYTES);

    int nsm = 148;
    cudaDeviceGetAttribute(&nsm, cudaDevAttrMultiProcessorCount, 0);
    if (nsm < 1) nsm = 148;

    norm_kernel<<<Nn / 8, 256>>>(q, c);
    simcse_main<<<nsm, 256, SMEM_BYTES>>>();
    loss_kernel<<<1, 1024>>>(out);
}

// round 16
// speedup vs baseline: 1.0053x; 1.0053x over previous
#include <cuda_runtime.h>
#include <cuda_bf16.h>
#include <cstdint>

// ===================== problem constants =====================
constexpr int Nn = 8192;
constexpr int Dd = 768;
constexpr int BM = 128;            // Q rows per job
constexpr int BN = 128;            // C cols per tile
constexpr int BK = 64;             // K per SMEM chunk (64 bf16 = 128B rows)
constexpr int NKC = Dd / BK;       // 12 K-chunks
constexpr int COLSPLIT = 16;       // by range
constexpr int CHUNKS = (Nn / BN) / COLSPLIT;  // 4 col tiles per job
constexpr int TOT = CHUNKS * NKC;  // 48 B-chunk iterations per job
constexpr int NJOBS = (Nn / BM) * COLSPLIT;   // 1024
// q rows pre-scaled by 20*log2(e): accumulators are base-2 logits directly
constexpr float QSCALE = 20.0f * 1.4426950408889634f;
constexpr float D2SC = 28.853900817779268f;   // 20*log2(e)
constexpr float LN2 = 0.6931471805599453f;

constexpr int A_BYTES = BM * Dd * 2;                    // 196608
constexpr int B_OFF   = A_BYTES;
constexpr int SMEM_BYTES = A_BYTES + 2 * BN * BK * 2;   // 229376

// ===================== device scratch =====================
__device__ __align__(16) __nv_bfloat16 g_qn[(size_t)Nn * Dd];
__device__ __align__(16) __nv_bfloat16 g_cn[(size_t)Nn * Dd];
__device__ float g_rows[COLSPLIT][Nn];
__device__ float g_diag[Nn];   // exact fp32 diagonal, base-2 scaled

// ===================== helpers =====================
__device__ __forceinline__ uint32_t smem_u32(const void* p) {
    uint32_t a;
    asm("{ .reg .u64 t; cvta.to.shared.u64 t, %1; cvt.u32.u64 %0, t; }"
        : "=r"(a) : "l"(p));
    return a;
}

#define SMEM_SWIZZLE_128B(o) ((o) ^ (((o) >> 3) & 0x70))

__device__ __forceinline__ void cp16(uint32_t dst, const void* src) {
    asm volatile("cp.async.cg.shared.global [%0], [%1], 16;" :: "r"(dst), "l"(src));
}
#define CP_COMMIT asm volatile("cp.async.commit_group;" ::: "memory")
#define CP_WAIT0  asm volatile("cp.async.wait_group 0;" ::: "memory")

__device__ __forceinline__ void ldm4(uint32_t* r, uint32_t addr) {
    asm volatile("ldmatrix.sync.aligned.m8n8.x4.shared.b16 {%0,%1,%2,%3}, [%4];"
        : "=r"(r[0]), "=r"(r[1]), "=r"(r[2]), "=r"(r[3]) : "r"(addr));
}

__device__ __forceinline__ void mma16816(float* d, const uint32_t* a,
                                         uint32_t b0, uint32_t b1) {
    asm volatile(
        "mma.sync.aligned.m16n8k16.row.col.f32.bf16.bf16.f32 "
        "{%0,%1,%2,%3}, {%4,%5,%6,%7}, {%8,%9}, {%0,%1,%2,%3};"
        : "+f"(d[0]), "+f"(d[1]), "+f"(d[2]), "+f"(d[3])
        : "r"(a[0]), "r"(a[1]), "r"(a[2]), "r"(a[3]), "r"(b0), "r"(b1));
}

__device__ __forceinline__ float ex2f(float x) {
    float y;
    asm("ex2.approx.f32 %0, %1;" : "=f"(y) : "f"(x));
    return y;
}

// ===== kernel 1: normalize fp32 -> bf16 (q pre-scaled), exact diagonal =====
// One warp per row (R14 single-pass). Each lane owns 8 consecutive elements
// per step -> one uint4 (16B) bf16 store instead of two uint2 stores.
__global__ void __launch_bounds__(256) norm_kernel(const float* __restrict__ q,
                                                   const float* __restrict__ c) {
    const int lane = threadIdx.x & 31;
    const int row = blockIdx.x * 8 + (threadIdx.x >> 5);  // 0..8191

    const float4* qs = reinterpret_cast<const float4*>(q + (size_t)row * Dd);
    const float4* cs = reinterpret_cast<const float4*>(c + (size_t)row * Dd);

    float4 qv[3][2], cv[3][2];
    float qq = 0.f, cc = 0.f, qc = 0.f;
#pragma unroll
    for (int j = 0; j < 3; j++) {
#pragma unroll
        for (int h = 0; h < 2; h++) {
            float4 a = qs[j * 64 + lane * 2 + h];
            float4 b = cs[j * 64 + lane * 2 + h];
            qv[j][h] = a;
            cv[j][h] = b;
            qq += a.x * a.x + a.y * a.y + a.z * a.z + a.w * a.w;
            cc += b.x * b.x + b.y * b.y + b.z * b.z + b.w * b.w;
            qc += a.x * b.x + a.y * b.y + a.z * b.z + a.w * b.w;
        }
    }
#pragma unroll
    for (int o = 16; o; o >>= 1) {
        qq += __shfl_xor_sync(0xFFFFFFFFu, qq, o);
        cc += __shfl_xor_sync(0xFFFFFFFFu, cc, o);
        qc += __shfl_xor_sync(0xFFFFFFFFu, qc, o);
    }
    const float nq = fmaxf(sqrtf(qq), 1e-8f);
    const float nc = fmaxf(sqrtf(cc), 1e-8f);
    if (lane == 0) g_diag[row] = D2SC * qc / (nq * nc);

    const float sq = QSCALE / nq, sc = 1.0f / nc;
    uint4* qd = reinterpret_cast<uint4*>(g_qn + (size_t)row * Dd);
    uint4* cd = reinterpret_cast<uint4*>(g_cn + (size_t)row * Dd);
#pragma unroll
    for (int j = 0; j < 3; j++) {
        __nv_bfloat162 p0 = __float22bfloat162_rn(
            make_float2(qv[j][0].x * sq, qv[j][0].y * sq));
        __nv_bfloat162 p1 = __float22bfloat162_rn(
            make_float2(qv[j][0].z * sq, qv[j][0].w * sq));
        __nv_bfloat162 p2 = __float22bfloat162_rn(
            make_float2(qv[j][1].x * sq, qv[j][1].y * sq));
        __nv_bfloat162 p3 = __float22bfloat162_rn(
            make_float2(qv[j][1].z * sq, qv[j][1].w * sq));
        qd[j * 32 + lane] = make_uint4(*(uint32_t*)&p0, *(uint32_t*)&p1,
                                       *(uint32_t*)&p2, *(uint32_t*)&p3);
        __nv_bfloat162 r0 = __float22bfloat162_rn(
            make_float2(cv[j][0].x * sc, cv[j][0].y * sc));
        __nv_bfloat162 r1 = __float22bfloat162_rn(
            make_float2(cv[j][0].z * sc, cv[j][0].w * sc));
        __nv_bfloat162 r2 = __float22bfloat162_rn(
            make_float2(cv[j][1].x * sc, cv[j][1].y * sc));
        __nv_bfloat162 r3 = __float22bfloat162_rn(
            make_float2(cv[j][1].z * sc, cv[j][1].w * sc));
        cd[j * 32 + lane] = make_uint4(*(uint32_t*)&r0, *(uint32_t*)&r1,
                                       *(uint32_t*)&r2, *(uint32_t*)&r3);
    }
}

// ===================== kernel 2: persistent fused GEMM + exp2-rowsum =====================
// grid = #SMs. Contiguous job spans (bx-major) -> A-tile reuse.
// 8 warps: 4(M) x 2(N), 32x64 warp tiles. Tile epilogues are DEFERRED:
// acc is stashed into eacc at tile end and the exp2/rowsum work is spread
// over chunks kc=0..3 of the next tile (overlaps MUFU with tensor pipe).
__global__ void __launch_bounds__(256, 1) simcse_main() {
    extern __shared__ __align__(1024) uint8_t smem[];
    uint8_t* sA = smem;           // 12 chunks of [128 rows][128B] SW128 K-major
    uint8_t* sB = smem + B_OFF;   // 2 buffers of [128 rows][128B] SW128 K-major

    const int tid = threadIdx.x;
    const int lane = tid & 31;
    const int wid = tid >> 5;
    const int warp_m = wid >> 1;   // 0..3 (32 rows each)
    const int warp_n = wid & 1;    // 0..1 (64 cols each)

    const uint32_t sA_u = smem_u32(sA);
    const uint32_t sB_u = smem_u32(sB);

    // per-lane ldmatrix base offsets (bytes, pre-swizzle) — R2/R5-validated
    const uint32_t aoff0 = (uint32_t)((lane & 15) * 128 + (lane >> 4) * 16) +
                           (uint32_t)warp_m * 4096u;
    const uint32_t boff0 = (uint32_t)(((((lane >> 4) & 1) * 8) + (lane & 7)) * 128 +
                                      ((lane >> 3) & 1) * 16) +
                           (uint32_t)warp_n * 8192u;

    const int ncta = gridDim.x;
    const int lo = (int)(((long long)blockIdx.x * NJOBS) / ncta);
    const int hi = (int)(((long long)(blockIdx.x + 1) * NJOBS) / ncta);
    int prev_bx = -1;

    float acc[2][8][4];
    float eacc[2][8][4];
#pragma unroll
    for (int mt = 0; mt < 2; mt++)
#pragma unroll
        for (int nt = 0; nt < 8; nt++)
#pragma unroll
            for (int d = 0; d < 4; d++) acc[mt][nt][d] = 0.f;

#pragma unroll 1
    for (int job = lo; job < hi; job++) {
        const int bx = job >> 4;       // row block 0..63
        const int by = job & 15;       // col split 0..15

        // ---- stage A on bx change: 128 Q rows (192KB) via cp.async ----
        if (bx != prev_bx) {
            const __nv_bfloat16* qbase = g_qn + (size_t)bx * BM * Dd;
#pragma unroll 4
            for (int i = 0; i < 48; i++) {
                int idx = tid + i * 256;        // 0..12287 (16B units)
                int kc = idx >> 10;
                int pos = idx & 1023;
                int r = pos >> 3, c = pos & 7;
                const void* src = qbase + (size_t)r * Dd + kc * BK + c * 8;
                uint32_t dst = sA_u + kc * 16384 +
                               SMEM_SWIZZLE_128B((uint32_t)(r * 128 + c * 16));
                cp16(dst, src);
            }
            prev_bx = bx;
        }

        const __nv_bfloat16* cquad = g_cn + (size_t)by * CHUNKS * BN * Dd;

        auto loadB = [&](int g, int buf) {
            const int t = g / NKC, kc = g % NKC;
            const __nv_bfloat16* cb = cquad + (size_t)t * BN * Dd + kc * BK;
#pragma unroll
            for (int i = 0; i < 4; i++) {
                int pos = tid + i * 256;        // 0..1023
                int r = pos >> 3, c = pos & 7;
                cp16(sB_u + buf * 16384 +
                         SMEM_SWIZZLE_128B((uint32_t)(r * 128 + c * 16)),
                     cb + (size_t)r * Dd + c * 8);
            }
            CP_COMMIT;
        };

        loadB(0, 0);  // (A's cp.asyncs, if any, join this commit group)

        float rsum[2][2] = {{0.f, 0.f}, {0.f, 0.f}};
        bool pending = false;

        // one 64-K chunk: wait, publish, prefetch next B, ldm+mma
        auto chunk = [&](int g, int kc) {
            const int buf = g & 1;
            CP_WAIT0;            // this chunk's B tile (and A if staged) resident
            __syncthreads();     // publish buf to all threads; protect buf^1
            if (g + 1 < TOT) loadB(g + 1, buf ^ 1);

            const uint32_t abase = sA_u + (uint32_t)kc * 16384u;
            const uint32_t bbase = sB_u + (uint32_t)buf * 16384u;

            uint32_t a[2][2][4], b[2][4][4];
#pragma unroll
            for (int mt = 0; mt < 2; mt++)
                ldm4(a[0][mt], abase + SMEM_SWIZZLE_128B(aoff0 + (uint32_t)(mt * 2048)));
#pragma unroll
            for (int ntp = 0; ntp < 4; ntp++)
                ldm4(b[0][ntp], bbase + SMEM_SWIZZLE_128B(boff0 + (uint32_t)(ntp * 2048)));

#pragma unroll
            for (int kk = 0; kk < 4; kk++) {
                const int cur = kk & 1, nxt = cur ^ 1;
                if (kk < 3) {
#pragma unroll
                    for (int mt = 0; mt < 2; mt++)
                        ldm4(a[nxt][mt], abase + SMEM_SWIZZLE_128B(
                                 aoff0 + (uint32_t)(mt * 2048 + (kk + 1) * 32)));
#pragma unroll
                    for (int ntp = 0; ntp < 4; ntp++)
                        ldm4(b[nxt][ntp], bbase + SMEM_SWIZZLE_128B(
                                 boff0 + (uint32_t)(ntp * 2048 + (kk + 1) * 32)));
                }
#pragma unroll
                for (int mt = 0; mt < 2; mt++)
#pragma unroll
                    for (int ntp = 0; ntp < 4; ntp++) {
                        mma16816(acc[mt][2 * ntp + 0], a[cur][mt],
                                 b[cur][ntp][0], b[cur][ntp][1]);
                        mma16816(acc[mt][2 * ntp + 1], a[cur][mt],
                                 b[cur][ntp][2], b[cur][ntp][3]);
                    }
            }
        };

#pragma unroll 1
        for (int t = 0; t < CHUNKS; t++) {
            // peeled kc=0..3: carry the previous tile's epilogue slices
#pragma unroll
            for (int kcp = 0; kcp < 4; kcp++) {
                chunk(t * NKC + kcp, kcp);
                if (pending) {
#pragma unroll
                    for (int mt = 0; mt < 2; mt++)
#pragma unroll
                        for (int j = 0; j < 2; j++) {
                            const int nt = 2 * kcp + j;  // static
#pragma unroll
                            for (int d = 0; d < 4; d++)
                                rsum[mt][d >> 1] += ex2f(eacc[mt][nt][d]);
                        }
                }
            }
#pragma unroll 1
            for (int kc = 4; kc < NKC; kc++) chunk(t * NKC + kc, kc);

            // tile end: stash accumulators, clear for next tile
#pragma unroll
            for (int mt = 0; mt < 2; mt++)
#pragma unroll
                for (int nt = 0; nt < 8; nt++)
#pragma unroll
                    for (int d = 0; d < 4; d++) {
                        eacc[mt][nt][d] = acc[mt][nt][d];
                        acc[mt][nt][d] = 0.f;
                    }
            pending = true;
        }

        // final (non-overlapped) epilogue for the job's last tile
#pragma unroll
        for (int mt = 0; mt < 2; mt++)
#pragma unroll
            for (int nt = 0; nt < 8; nt++)
#pragma unroll
                for (int d = 0; d < 4; d++)
                    rsum[mt][d >> 1] += ex2f(eacc[mt][nt][d]);

        // ---- per-job reduce: quad shuffle, then across the 2 N-warps ----
#pragma unroll
        for (int mt = 0; mt < 2; mt++)
#pragma unroll
            for (int h = 0; h < 2; h++) {
                float v = rsum[mt][h];
                v += __shfl_xor_sync(0xFFFFFFFFu, v, 1);
                v += __shfl_xor_sync(0xFFFFFFFFu, v, 2);
                rsum[mt][h] = v;
            }

        float* sred = (float*)sB;    // B buffers are free after last chunk
        __syncthreads();             // all warps done with compute/B reads
        if ((lane & 3) == 0) {
#pragma unroll
            for (int mt = 0; mt < 2; mt++)
#pragma unroll
                for (int h = 0; h < 2; h++) {
                    int rl = warp_m * 32 + mt * 16 + h * 8 + (lane >> 2);
                    sred[rl * 2 + warp_n] = rsum[mt][h];
                }
        }
        __syncthreads();
        if (tid < BM) g_rows[by][bx * BM + tid] = sred[tid * 2] + sred[tid * 2 + 1];
        __syncthreads();  // sred reads done before next job's loadB overwrites sB
    }
}

// ===================== kernel 3: loss reduction (1024 threads) =====================
__global__ void __launch_bounds__(1024) loss_kernel(float* __restrict__ out) {
    int tid = threadIdx.x;
    float acc = 0.f;
#pragma unroll 1
    for (int i = tid; i < Nn; i += 1024) {
        float r = 0.f;
#pragma unroll
        for (int s = 0; s < COLSPLIT; s++) r += g_rows[s][i];
        acc += logf(r) - g_diag[i] * LN2;   // diag is base-2 scaled (exact fp32)
    }
#pragma unroll
    for (int o = 16; o; o >>= 1) acc += __shfl_xor_sync(0xFFFFFFFFu, acc, o);
    __shared__ float sred[32];
    if ((tid & 31) == 0) sred[tid >> 5] = acc;
    __syncthreads();
    if (tid < 32) {
        float v = sred[tid];
#pragma unroll
        for (int o = 16; o; o >>= 1) v += __shfl_xor_sync(0xFFFFFFFFu, v, o);
        if (tid == 0) out[0] = v * (1.0f / (float)Nn);
    }
}

// ===================== launch =====================
extern "C" void kernel_launch(void* const* d_in, const int* in_sizes, int n_in,
                              void* d_out, int out_size) {
    const float* q = (const float*)d_in[0];
    const float* c = (const float*)d_in[1];
    float* out = (float*)d_out;

    cudaFuncSetAttribute(simcse_main, cudaFuncAttributeMaxDynamicSharedMemorySize,
                         SMEM_BYTES);

    int nsm = 148;
    cudaDeviceGetAttribute(&nsm, cudaDevAttrMultiProcessorCount, 0);
    if (nsm < 1) nsm = 148;

    norm_kernel<<<Nn / 8, 256>>>(q, c);
    simcse_main<<<nsm, 256, SMEM_BYTES>>>();
    loss_kernel<<<1, 1024>>>(out);
}